// round 15
// baseline (speedup 1.0000x reference)
#include <cuda_runtime.h>
#include <cuda_bf16.h>
#include <math.h>

// Global accumulators (zero at module load; last block resets each run).
__device__ float        g_bins[128];
__device__ float        g_cls_sum;
__device__ float        g_box_sum;
__device__ unsigned int g_arrive;

// ---------------------------------------------------------------------------
// Heterogeneous single launch, 128-thread blocks:
//   blocks [0, R):        mask BCE for RoI r = blockIdx.x.
//       4 warps; warp w owns grid rows 7w..7w+6; lane = column (0..27).
//       ALL 35 loads (28 gathers + 7 sel) issued before any consume.
//   blocks [R, R+R/4):    CE + box. Warp w handles row (blockIdx.x-R)*4 + w.
//   Epilogue: tid0 atomics + single release-arrive (program order).
//   LAST block: histogram counts, __ldcg reads, writes 102 outputs, resets.
// ---------------------------------------------------------------------------
template<int MO, int WSHIFT>
__global__ void __launch_bounds__(128, 6) fused_kernel(
        const float* __restrict__ class_logit,
        const float* __restrict__ box_regression,
        const float* __restrict__ regression_target,
        const float* __restrict__ mask_logit,
        const float* __restrict__ proposal,
        const float* __restrict__ gt_mask,
        const int* __restrict__ matched_idx,
        const int* __restrict__ label,
        float* __restrict__ out,
        int C, int Hh_rt, int Ww_rt, int Mo_rt, int num_pos, int R, int G) {
    const int Mo = (MO > 0) ? MO : Mo_rt;
    const int P  = Mo * Mo;
    const int Hh = (WSHIFT > 0) ? (1 << WSHIFT) : Hh_rt;
    const int Ww = (WSHIFT > 0) ? (1 << WSHIFT) : Ww_rt;
    int tid  = threadIdx.x;
    int lane = tid & 31;
    int w    = tid >> 5;
    __shared__ float sh[4];
    __shared__ float sh2[4];
    __shared__ bool  s_last;
    __shared__ int   s_cnt[128];

    if (blockIdx.x < (unsigned)R) {
        // ================= MASK BLOCK =================
        int r   = blockIdx.x;
        int lab = __ldg(&label[r]);
        int b   = __ldg(&matched_idx[r]);

        float acc  = 0.0f;
        float prod = 1.0f;
        float4 box = *(const float4*)(proposal + r * 4);
        float x1 = box.x, y1 = box.y, x2 = box.z, y2 = box.w;
        float invMo = 1.0f / (float)Mo;
        float sx = (x2 - x1) * invMo;
        float sy = (y2 - y1) * invMo;
        const float* sel = mask_logit + (r * C + lab) * P;
        const float* fm  = gt_mask + b * (Hh * Ww);

        if (MO == 28) {
            const int ix = lane;                 // lanes 0..27 active
            const bool active = ix < 28;

            // x geometry: row-invariant
            float x  = fmaf((float)ix + 0.5f, sx, x1);
            bool  vx = (x > -1.0f) & (x < (float)Ww);
            float xc = fminf(fmaxf(x, 0.0f), (float)(Ww - 1));
            int   x0 = (int)xc;
            int   xi = min(x0 + 1, Ww - 1);
            float lx = xc - (float)x0;

            // phase 1: geometry for this warp's 7 rows
            float ly[7]; bool vrow[7];
            int o0[7], o1[7];
            #pragma unroll
            for (int i = 0; i < 7; i++) {
                int row = w * 7 + i;
                float y = fmaf((float)row + 0.5f, sy, y1);
                vrow[i] = active & vx & (y > -1.0f) & (y < (float)Hh);
                float yc = fminf(fmaxf(y, 0.0f), (float)(Hh - 1));
                int y0 = (int)yc;
                int yi = min(y0 + 1, Hh - 1);
                ly[i] = yc - (float)y0;
                if (WSHIFT > 0) { o0[i] = y0 << WSHIFT; o1[i] = yi << WSHIFT; }
                else            { o0[i] = y0 * Ww;      o1[i] = yi * Ww;      }
            }
            // phase 2: issue ALL 35 loads before any consume
            float v00[7], v01[7], v10[7], v11[7], sl[7];
            #pragma unroll
            for (int i = 0; i < 7; i++) {
                v00[i] = __ldg(fm + o0[i] + x0);
                v01[i] = __ldg(fm + o0[i] + xi);
                v10[i] = __ldg(fm + o1[i] + x0);
                v11[i] = __ldg(fm + o1[i] + xi);
            }
            #pragma unroll
            for (int i = 0; i < 7; i++) {
                int row = w * 7 + i;
                sl[i] = active ? __ldg(sel + row * 28 + ix) : 0.0f;
            }
            // phase 3: consume
            #pragma unroll
            for (int i = 0; i < 7; i++) {
                float top = fmaf(lx, v01[i] - v00[i], v00[i]);
                float bot = fmaf(lx, v11[i] - v10[i], v10[i]);
                float t = fmaf(ly[i], bot - top, top);
                t = vrow[i] ? t : 0.0f;
                float s = sl[i];
                acc += fmaxf(s, 0.0f) - s * t;
                float f = 1.0f + __expf(-fabsf(s));
                prod *= active ? f : 1.0f;
            }
        } else {
            for (int p = tid; p < P; p += 128) {
                int iy = p / Mo;
                int ix = p - iy * Mo;
                float x = fmaf((float)ix + 0.5f, sx, x1);
                float y = fmaf((float)iy + 0.5f, sy, y1);
                bool valid = (x > -1.0f) & (x < (float)Ww) & (y > -1.0f) & (y < (float)Hh);
                float xc = fminf(fmaxf(x, 0.0f), (float)(Ww - 1));
                float yc = fminf(fmaxf(y, 0.0f), (float)(Hh - 1));
                int x0 = (int)xc, y0 = (int)yc;
                int xi = min(x0 + 1, Ww - 1);
                int yi = min(y0 + 1, Hh - 1);
                float lx = xc - (float)x0, ly = yc - (float)y0;
                const float* r0 = fm + y0 * Ww;
                const float* r1 = fm + yi * Ww;
                float v00 = __ldg(r0 + x0), v01 = __ldg(r0 + xi);
                float v10 = __ldg(r1 + x0), v11 = __ldg(r1 + xi);
                float top = fmaf(lx, v01 - v00, v00);
                float bot = fmaf(lx, v11 - v10, v10);
                float t = fmaf(ly, bot - top, top);
                t = valid ? t : 0.0f;
                float s = __ldg(sel + p);
                acc  += fmaxf(s, 0.0f) - s * t;
                prod *= 1.0f + __expf(-fabsf(s));
            }
        }

        // product across 8-lane groups (<= 2^56 in fp32: safe)
        #pragma unroll
        for (int o = 1; o < 8; o <<= 1) prod *= __shfl_xor_sync(0xFFFFFFFFu, prod, o);
        if ((lane & 7) == 0) acc += __logf(prod);

        #pragma unroll
        for (int o = 16; o; o >>= 1) acc += __shfl_xor_sync(0xFFFFFFFFu, acc, o);
        if (lane == 0) sh[w] = acc;
        __syncthreads();

        if (w == 0 && lane == 0) {
            float v = sh[0] + sh[1] + sh[2] + sh[3];
            atomicAdd(&g_bins[b], v / (float)P);
            unsigned int n;
            asm volatile("atom.release.gpu.global.add.u32 %0, [%1], 1;"
                         : "=r"(n) : "l"(&g_arrive) : "memory");
            s_last = (n == (unsigned int)(gridDim.x - 1));
        }
    } else {
        // ================= CE/BOX BLOCK =================
        int rr = (blockIdx.x - R) * 4 + w;
        float cls_t = 0.0f, box_t = 0.0f;
        if (rr < R) {
            int lab = __ldg(&label[rr]);
            const float* row = class_logit + rr * C;
            float e0 = (lane      < C) ? __ldg(row + lane)      : -INFINITY;
            float e1 = (lane + 32 < C) ? __ldg(row + lane + 32) : -INFINITY;
            float e2 = (lane + 64 < C) ? __ldg(row + lane + 64) : -INFINITY;
            float mx = fmaxf(e0, fmaxf(e1, e2));
            #pragma unroll
            for (int o = 16; o; o >>= 1) mx = fmaxf(mx, __shfl_xor_sync(0xFFFFFFFFu, mx, o));
            float s2 = 0.0f;
            if (lane      < C) s2 += __expf(e0 - mx);
            if (lane + 32 < C) s2 += __expf(e1 - mx);
            if (lane + 64 < C) s2 += __expf(e2 - mx);
            #pragma unroll
            for (int o = 16; o; o >>= 1) s2 += __shfl_xor_sync(0xFFFFFFFFu, s2, o);
            if (lane == 0) cls_t = mx + __logf(s2) - __ldg(row + lab);

            if (rr < num_pos) {
                float term = 0.0f;
                if (lane < 4) {
                    float pred = __ldg(&box_regression[rr * (C * 4) + lab * 4 + lane]);
                    float tgt  = __ldg(&regression_target[rr * 4 + lane]);
                    float d = fabsf(pred - tgt);
                    term = (d < 1.0f) ? 0.5f * d * d : d - 0.5f;
                }
                #pragma unroll
                for (int o = 2; o; o >>= 1) term += __shfl_xor_sync(0xFFFFFFFFu, term, o);
                if (lane == 0) box_t = term;
            }
        }
        if (lane == 0) { sh[w] = cls_t; sh2[w] = box_t; }
        __syncthreads();

        if (w == 0 && lane == 0) {
            atomicAdd(&g_cls_sum, sh[0] + sh[1] + sh[2] + sh[3]);
            float bx = sh2[0] + sh2[1] + sh2[2] + sh2[3];
            if (bx != 0.0f) atomicAdd(&g_box_sum, bx);
            unsigned int n;
            asm volatile("atom.release.gpu.global.add.u32 %0, [%1], 1;"
                         : "=r"(n) : "l"(&g_arrive) : "memory");
            s_last = (n == (unsigned int)(gridDim.x - 1));
        }
    }
    __syncthreads();

    if (s_last) {
        // per-gt counts: smem histogram of matched_idx
        s_cnt[tid] = 0;
        __syncthreads();
        for (int i = tid; i < R; i += 128)
            atomicAdd(&s_cnt[__ldg(&matched_idx[i])], 1);
        __syncthreads();
        // Accumulators are L2-resident atomic results; __ldcg reads L2 directly.
        if (tid == 0) out[0] = __ldcg(&g_cls_sum) / (float)R;
        if (tid == 1) out[1] = __ldcg(&g_box_sum) / (float)R;
        if (tid < G) {
            int c = s_cnt[tid];
            float bsum = __ldcg(&g_bins[tid]);
            out[2 + tid] = (c > 0) ? bsum / (float)c : 0.0f;
        }
        __syncthreads();
        // reset for next graph replay
        if (tid == 0) { g_cls_sum = 0.0f; g_box_sum = 0.0f; g_arrive = 0u; }
        g_bins[tid] = 0.0f;
    }
}

// ---------------------------------------------------------------------------
// Launch
// ---------------------------------------------------------------------------
extern "C" void kernel_launch(void* const* d_in, const int* in_sizes, int n_in,
                              void* d_out, int out_size) {
    const float* class_logit       = (const float*)d_in[0];
    const float* box_regression    = (const float*)d_in[1];
    const float* regression_target = (const float*)d_in[2];
    const float* mask_logit        = (const float*)d_in[3];
    const float* proposal          = (const float*)d_in[4];
    const float* gt_mask           = (const float*)d_in[5];
    const int*   matched_idx       = (const int*)d_in[6];
    const int*   label             = (const int*)d_in[7];
    float* out = (float*)d_out;

    int R = in_sizes[4] / 4;                         // proposal [R,4]
    int C = in_sizes[0] / R;                         // class_logit [R,C]
    int num_pos = in_sizes[2] / 4;                   // regression_target [P,4]
    long long mm = (long long)in_sizes[3] / ((long long)R * C);
    int Mo = (int)(sqrtf((float)mm) + 0.5f);         // mask_logit [R,C,Mo,Mo]
    int G = out_size - 2;                            // per_gt bins
    long long hw = (long long)in_sizes[5] / G;       // gt_mask [G,H,W]
    int Hh = (int)(sqrtf((float)hw) + 0.5f);
    int Ww = Hh;

    int grid = R + (R + 3) / 4;   // mask blocks + CE blocks

    if (Mo == 28 && Ww == 512 && Hh == 512) {
        fused_kernel<28, 9><<<grid, 128>>>(class_logit, box_regression, regression_target,
                                           mask_logit, proposal, gt_mask,
                                           matched_idx, label, out,
                                           C, Hh, Ww, Mo, num_pos, R, G);
    } else if (Mo == 28) {
        fused_kernel<28, 0><<<grid, 128>>>(class_logit, box_regression, regression_target,
                                           mask_logit, proposal, gt_mask,
                                           matched_idx, label, out,
                                           C, Hh, Ww, Mo, num_pos, R, G);
    } else {
        fused_kernel<0, 0><<<grid, 128>>>(class_logit, box_regression, regression_target,
                                          mask_logit, proposal, gt_mask,
                                          matched_idx, label, out,
                                          C, Hh, Ww, Mo, num_pos, R, G);
    }
}